// round 1
// baseline (speedup 1.0000x reference)
#include <cuda_runtime.h>
#include <math.h>

#define N_ROWS 8192
#define T_COLS 256

// Scratch (allocation-free: __device__ globals)
__device__ float g_B [T_COLS * T_COLS];   // B[d][t]  = sum over rows j with dur_j==d of exp(2*cdf[j,t])
__device__ float g_B0[T_COLS * T_COLS];   // same, restricted to ev_j==0
__device__ float g_SS[T_COLS * T_COLS];   // SS[d][t] = B0[d][t] + sum_{d'>d} B[d'][t]
__device__ float g_nll[N_ROWS];           // per-row NLL contribution
__device__ float g_w  [N_ROWS];           // ev_i ? exp(-2*A_i) : 0

__device__ __forceinline__ float warp_max(float v) {
    #pragma unroll
    for (int o = 16; o > 0; o >>= 1)
        v = fmaxf(v, __shfl_xor_sync(0xffffffffu, v, o));
    return v;
}

__global__ void zero_kernel() {
    int i = blockIdx.x * blockDim.x + threadIdx.x;   // 65536 threads
    g_B[i]  = 0.0f;
    g_B0[i] = 0.0f;
}

// One warp per row. Each lane owns 8 contiguous columns (2x float4 loads).
__global__ void __launch_bounds__(256) row_kernel(
    const float* __restrict__ hz,
    const int*   __restrict__ dur,
    const int*   __restrict__ ev,
    const int*   __restrict__ lab)
{
    const int gwarp = (blockIdx.x * blockDim.x + threadIdx.x) >> 5;
    const int lane  = threadIdx.x & 31;
    if (gwarp >= N_ROWS) return;

    const float4* rp = reinterpret_cast<const float4*>(hz + (size_t)gwarp * T_COLS);
    float4 a = rp[lane * 2];
    float4 b = rp[lane * 2 + 1];
    float v[8] = {a.x, a.y, a.z, a.w, b.x, b.y, b.z, b.w};

    // row max (phi includes a padded 0 column -> clamp at 0)
    float m = v[0];
    #pragma unroll
    for (int k = 1; k < 8; k++) m = fmaxf(m, v[k]);
    const float gamma = fmaxf(warp_max(m), 0.0f);

    // exp and local prefix
    float e[8];
    float local = 0.0f;
    #pragma unroll
    for (int k = 0; k < 8; k++) { e[k] = __expf(v[k] - gamma); local += e[k]; }

    // warp inclusive scan of per-lane totals
    float incl = local;
    #pragma unroll
    for (int o = 1; o < 32; o <<= 1) {
        float t = __shfl_up_sync(0xffffffffu, incl, o);
        if (lane >= o) incl += t;
    }
    const float total = __shfl_sync(0xffffffffu, incl, 31);
    const float offs  = incl - local;          // exclusive prefix for this lane

    float scan[8];
    {
        float run = offs;
        #pragma unroll
        for (int k = 0; k < 8; k++) { run += e[k]; scan[k] = run; }
    }

    const float sum_ = total + __expf(-gamma);  // pad column exp(0-gamma)
    const float inv  = 1.0f / sum_;

    const int d   = dur[gwarp];
    const int evv = ev[gwarp];
    const int L   = lab[gwarp];

    // accumulate exp(2*cdf[row, t]) into duration-binned tables
    float* Brow  = g_B  + d * T_COLS;
    float* B0row = g_B0 + d * T_COLS;
    #pragma unroll
    for (int k = 0; k < 8; k++) {
        const int t = lane * 8 + k;
        const float w = __expf(2.0f * scan[k] * inv);   // sigma = 0.5 -> exp(cdf/sigma)
        atomicAdd(Brow + t, w);
        if (evv == 0) atomicAdd(B0row + t, w);
    }

    // pull cumsum[L] and phi[L] from the owning lane (L is warp-uniform)
    const int kk = L & 7;
    float cum_sel = scan[0];
    float phi_sel = v[0];
    #pragma unroll
    for (int k = 1; k < 8; k++) {
        if (kk == k) { cum_sel = scan[k]; phi_sel = v[k]; }
    }
    const float cum_at = __shfl_sync(0xffffffffu, cum_sel, L >> 3);
    const float phi_at = __shfl_sync(0xffffffffu, phi_sel, L >> 3);

    if (lane == 0) {
        const float EPS = 1e-7f;
        const float evf = (evv != 0) ? 1.0f : 0.0f;
        const float part1 = (phi_at - gamma) * evf;
        const float part2 = -logf(fmaxf(sum_, 0.0f) + EPS);
        const float part3 = logf(fmaxf(sum_ - cum_at, 0.0f) + EPS) * (1.0f - evf);
        g_nll[gwarp] = -(part1 + part2 + part3);
        const float A = cum_at * inv;            // cdf[i, lab[i]]
        g_w[gwarp] = (evv != 0) ? __expf(-2.0f * A) : 0.0f;
    }
}

// SS[d][t] = B0[d][t] + sum_{d' > d} B[d'][t].  One block, one thread per column t.
__global__ void __launch_bounds__(256) suffix_kernel() {
    const int t = threadIdx.x;
    float suf = 0.0f;
    for (int d = T_COLS - 1; d >= 0; --d) {
        g_SS[d * T_COLS + t] = g_B0[d * T_COLS + t] + suf;
        suf += g_B[d * T_COLS + t];
    }
}

// Final reduction: nll mean + rank mean -> scalar
__global__ void __launch_bounds__(1024) final_kernel(
    const int* __restrict__ dur,
    const int* __restrict__ lab,
    float* __restrict__ out)
{
    __shared__ float s1[1024];
    __shared__ float s2[1024];
    const int tid = threadIdx.x;

    float nll = 0.0f, rank = 0.0f;
    #pragma unroll
    for (int i = tid; i < N_ROWS; i += 1024) {
        nll += g_nll[i];
        const float w = g_w[i];
        if (w != 0.0f)
            rank += w * g_SS[dur[i] * T_COLS + lab[i]];
    }
    s1[tid] = nll;
    s2[tid] = rank;
    __syncthreads();
    #pragma unroll
    for (int s = 512; s > 0; s >>= 1) {
        if (tid < s) { s1[tid] += s1[tid + s]; s2[tid] += s2[tid + s]; }
        __syncthreads();
    }
    if (tid == 0) {
        const float ALPHA = 0.5f;
        const float nll_mean  = s1[0] / (float)N_ROWS;
        const float rank_mean = s2[0] / ((float)N_ROWS * (float)N_ROWS);
        out[0] = ALPHA * nll_mean + (1.0f - ALPHA) * rank_mean;
    }
}

extern "C" void kernel_launch(void* const* d_in, const int* in_sizes, int n_in,
                              void* d_out, int out_size)
{
    const float* hz  = (const float*)d_in[0];
    const int*   dur = (const int*)  d_in[1];
    const int*   ev  = (const int*)  d_in[2];
    const int*   lab = (const int*)  d_in[3];
    float* out = (float*)d_out;

    zero_kernel  <<<(T_COLS * T_COLS) / 256, 256>>>();
    row_kernel   <<<(N_ROWS * 32) / 256, 256>>>(hz, dur, ev, lab);
    suffix_kernel<<<1, 256>>>();
    final_kernel <<<1, 1024>>>(dur, lab, out);
}

// round 2
// speedup vs baseline: 4.7130x; 4.7130x over previous
#include <cuda_runtime.h>
#include <math.h>

#define N_ROWS 8192
#define T_COLS 256

// Scratch (allocation-free: __device__ globals)
// g_BB[t][d] = { B, B0 } transposed+interleaved:
//   B [d][t] = sum over rows j with dur_j==d of exp(2*cdf[j,t])
//   B0[d][t] = same, restricted to ev_j==0
__device__ float2 g_BB[T_COLS * T_COLS];
__device__ float  g_SS[T_COLS * T_COLS];   // SS[t][d] = B0[d][t] + sum_{d'>d} B[d'][t]
__device__ float  g_nll[N_ROWS];           // per-row NLL contribution
__device__ float  g_w  [N_ROWS];           // ev_i ? exp(-2*A_i) : 0
__device__ float  g_acc[2];                // {nll_sum, rank_sum}
__device__ unsigned int g_tickets;

__device__ __forceinline__ float warp_max(float v) {
    #pragma unroll
    for (int o = 16; o > 0; o >>= 1)
        v = fmaxf(v, __shfl_xor_sync(0xffffffffu, v, o));
    return v;
}

__global__ void zero_kernel() {
    int i = blockIdx.x * blockDim.x + threadIdx.x;   // 32768 threads x float4
    reinterpret_cast<float4*>(g_BB)[i] = make_float4(0.f, 0.f, 0.f, 0.f);
    if (i == 0) { g_acc[0] = 0.f; g_acc[1] = 0.f; g_tickets = 0u; }
}

// One warp per row. Each lane owns 8 contiguous columns (2x float4 loads).
__global__ void __launch_bounds__(256) row_kernel(
    const float* __restrict__ hz,
    const int*   __restrict__ dur,
    const int*   __restrict__ ev,
    const int*   __restrict__ lab)
{
    const int gwarp = (blockIdx.x * blockDim.x + threadIdx.x) >> 5;
    const int lane  = threadIdx.x & 31;

    const float4* rp = reinterpret_cast<const float4*>(hz + (size_t)gwarp * T_COLS);
    float4 a = rp[lane * 2];
    float4 b = rp[lane * 2 + 1];
    float v[8] = {a.x, a.y, a.z, a.w, b.x, b.y, b.z, b.w};

    // row max (phi includes a padded 0 column -> clamp at 0)
    float m = v[0];
    #pragma unroll
    for (int k = 1; k < 8; k++) m = fmaxf(m, v[k]);
    const float gamma = fmaxf(warp_max(m), 0.0f);

    // exp and local prefix
    float e[8];
    float local = 0.0f;
    #pragma unroll
    for (int k = 0; k < 8; k++) { e[k] = __expf(v[k] - gamma); local += e[k]; }

    // warp inclusive scan of per-lane totals
    float incl = local;
    #pragma unroll
    for (int o = 1; o < 32; o <<= 1) {
        float t = __shfl_up_sync(0xffffffffu, incl, o);
        if (lane >= o) incl += t;
    }
    const float total = __shfl_sync(0xffffffffu, incl, 31);
    const float offs  = incl - local;          // exclusive prefix for this lane

    float scan[8];
    {
        float run = offs;
        #pragma unroll
        for (int k = 0; k < 8; k++) { run += e[k]; scan[k] = run; }
    }

    const float sum_ = total + __expf(-gamma);  // pad column exp(0-gamma)
    const float inv  = 1.0f / sum_;
    const float s2   = 2.0f * inv;              // sigma = 0.5 -> exp(cdf/sigma) = exp(2*cdf)

    const int d   = dur[gwarp];
    const int evv = ev[gwarp];
    const int L   = lab[gwarp];
    const float evmask = (evv == 0) ? 1.0f : 0.0f;

    // accumulate {exp(2*cdf), ev==0 ? exp(2*cdf) : 0} into transposed table g_BB[t][d]
    #pragma unroll
    for (int k = 0; k < 8; k++) {
        const int t = lane * 8 + k;
        const float w  = __expf(scan[k] * s2);
        const float w0 = w * evmask;
        float2* addr = &g_BB[t * T_COLS + d];
        asm volatile("red.global.add.v2.f32 [%0], {%1, %2};"
                     :: "l"(addr), "f"(w), "f"(w0) : "memory");
    }

    // pull cumsum[L] and phi[L] from the owning lane (L is warp-uniform)
    const int kk = L & 7;
    float cum_sel = scan[0];
    float phi_sel = v[0];
    #pragma unroll
    for (int k = 1; k < 8; k++) {
        if (kk == k) { cum_sel = scan[k]; phi_sel = v[k]; }
    }
    const float cum_at = __shfl_sync(0xffffffffu, cum_sel, L >> 3);
    const float phi_at = __shfl_sync(0xffffffffu, phi_sel, L >> 3);

    if (lane == 0) {
        const float EPS = 1e-7f;
        const float evf = (evv != 0) ? 1.0f : 0.0f;
        const float part1 = (phi_at - gamma) * evf;
        const float part2 = -logf(fmaxf(sum_, 0.0f) + EPS);
        const float part3 = logf(fmaxf(sum_ - cum_at, 0.0f) + EPS) * (1.0f - evf);
        g_nll[gwarp] = -(part1 + part2 + part3);
        const float A = cum_at * inv;            // cdf[i, lab[i]]
        g_w[gwarp] = (evv != 0) ? __expf(-2.0f * A) : 0.0f;
    }
}

// Parallel suffix-scan: one warp per column t. Lane owns 8 consecutive d.
// SS[t][d] = B0[d][t] + sum_{d' > d} B[d'][t]
__global__ void __launch_bounds__(256) suffix_kernel() {
    const int warp = threadIdx.x >> 5;
    const int lane = threadIdx.x & 31;
    const int t    = blockIdx.x * 8 + warp;

    // load 8 {B,B0} pairs (contiguous in transposed layout) via 4x float4
    const float4* cp = reinterpret_cast<const float4*>(&g_BB[t * T_COLS + lane * 8]);
    float4 p0 = cp[0], p1 = cp[1], p2 = cp[2], p3 = cp[3];
    float Bv [8] = {p0.x, p0.z, p1.x, p1.z, p2.x, p2.z, p3.x, p3.z};
    float B0v[8] = {p0.y, p0.w, p1.y, p1.w, p2.y, p2.w, p3.y, p3.w};

    float local = 0.0f;
    #pragma unroll
    for (int k = 0; k < 8; k++) local += Bv[k];

    // inclusive suffix scan over lanes
    float incl = local;
    #pragma unroll
    for (int o = 1; o < 32; o <<= 1) {
        float u = __shfl_down_sync(0xffffffffu, incl, o);
        if (lane < 32 - o) incl += u;
    }
    float run = incl - local;   // sum over lanes > lane

    float ss[8];
    #pragma unroll
    for (int k = 7; k >= 0; k--) {
        ss[k] = B0v[k] + run;
        run += Bv[k];
    }
    float4* op = reinterpret_cast<float4*>(&g_SS[t * T_COLS + lane * 8]);
    op[0] = make_float4(ss[0], ss[1], ss[2], ss[3]);
    op[1] = make_float4(ss[4], ss[5], ss[6], ss[7]);
}

// Final reduction: 8 blocks x 1024 threads, one row each; last block writes out.
__global__ void __launch_bounds__(1024) final_kernel(
    const int* __restrict__ dur,
    const int* __restrict__ lab,
    float* __restrict__ out)
{
    __shared__ float s1[32];
    __shared__ float s2[32];
    const int i    = blockIdx.x * 1024 + threadIdx.x;
    const int lane = threadIdx.x & 31;
    const int warp = threadIdx.x >> 5;

    float nll  = g_nll[i];
    const float w = g_w[i];
    float rank = (w != 0.0f) ? w * g_SS[lab[i] * T_COLS + dur[i]] : 0.0f;

    #pragma unroll
    for (int o = 16; o > 0; o >>= 1) {
        nll  += __shfl_xor_sync(0xffffffffu, nll,  o);
        rank += __shfl_xor_sync(0xffffffffu, rank, o);
    }
    if (lane == 0) { s1[warp] = nll; s2[warp] = rank; }
    __syncthreads();
    if (warp == 0) {
        nll  = s1[lane];
        rank = s2[lane];
        #pragma unroll
        for (int o = 16; o > 0; o >>= 1) {
            nll  += __shfl_xor_sync(0xffffffffu, nll,  o);
            rank += __shfl_xor_sync(0xffffffffu, rank, o);
        }
        if (lane == 0) {
            atomicAdd(&g_acc[0], nll);
            atomicAdd(&g_acc[1], rank);
            __threadfence();
            unsigned int tk = atomicAdd(&g_tickets, 1u);
            if (tk == gridDim.x - 1) {
                const float ALPHA = 0.5f;
                const float nll_mean  = g_acc[0] / (float)N_ROWS;
                const float rank_mean = g_acc[1] / ((float)N_ROWS * (float)N_ROWS);
                out[0] = ALPHA * nll_mean + (1.0f - ALPHA) * rank_mean;
            }
        }
    }
}

extern "C" void kernel_launch(void* const* d_in, const int* in_sizes, int n_in,
                              void* d_out, int out_size)
{
    const float* hz  = (const float*)d_in[0];
    const int*   dur = (const int*)  d_in[1];
    const int*   ev  = (const int*)  d_in[2];
    const int*   lab = (const int*)  d_in[3];
    float* out = (float*)d_out;

    zero_kernel  <<<128, 256>>>();                         // 32768 float4 stores
    row_kernel   <<<(N_ROWS * 32) / 256, 256>>>(hz, dur, ev, lab);
    suffix_kernel<<<T_COLS / 8, 256>>>();
    final_kernel <<<N_ROWS / 1024, 1024>>>(dur, lab, out);
}